// round 14
// baseline (speedup 1.0000x reference)
#include <cuda_runtime.h>
#include <cstdint>

#define CPS    16
#define ENC    128
#define BATCH  4
#define HW     160
#define PLANE  (HW * HW)          // 25600
#define NGRID  10
#define NPATCH 100
#define NROWS  (BATCH * NPATCH)   // 400
#define CCH    256
#define BR     8                  // rows per MLP block
#define NHELP  8                  // transpose helper blocks per branch

// Scratch (allocation-free)
__device__ float g_X[2][NROWS * CCH];          // conv output, patch-major
__device__ float g_E[2][NROWS * ENC];          // embeddings
__device__ float g_W1T[2][CCH * CCH];          // W1 transposed: [k][j]
__device__ float g_W2T[2][CCH * ENC];          // W2 transposed: [k][o]

// ---------------------------------------------------------------------------
// Kernel A: R7-proven conv (bx < 200) + parallel smem-tiled weight transpose
// (bx in [200, 208)). Conv: 256 thr x float2 = 2KB grain per channel step,
// __ldcs evict-first, 400 conv blocks (~21.6 warps/SM plateau). Helpers:
// 32x32 smem tiles, coalesced read AND write, ~2us across 16 SMs — hidden
// under the 41us HBM-bound conv.
// ---------------------------------------------------------------------------
__global__ void conv_kernel(const float* __restrict__ f1,
                            const float* __restrict__ f2,
                            const float* __restrict__ w_img,
                            const float* __restrict__ b_img,
                            const float* __restrict__ w_dep,
                            const float* __restrict__ b_dep,
                            const float* __restrict__ iw1,
                            const float* __restrict__ iw2,
                            const float* __restrict__ dw1,
                            const float* __restrict__ dw2)
{
    const int br  = blockIdx.y;
    const int tid = threadIdx.x;

    __shared__ float ws[CCH];
    __shared__ float tile[32][33];

    if (blockIdx.x >= 200) {
        // ---- parallel weight transpose helpers (8 blocks per branch) ----
        const int hb = blockIdx.x - 200;                  // 0..7
        const float* __restrict__ W1 = br ? dw1 : iw1;    // [j][k] 256x256
        const float* __restrict__ W2 = br ? dw2 : iw2;    // [o][k] 128x256
        float* __restrict__ W1T = g_W1T[br];
        float* __restrict__ W2T = g_W2T[br];
        const int ty = tid >> 5;                          // 0..7
        const int tx = tid & 31;

        // W1: 8x8 = 64 tiles of 32x32
        for (int t = hb; t < 64; t += NHELP) {
            const int tr = t >> 3, tc = t & 7;
            #pragma unroll
            for (int rr = 0; rr < 4; rr++) {
                int r = rr * 8 + ty;
                tile[r][tx] = W1[(tr * 32 + r) * CCH + tc * 32 + tx];
            }
            __syncthreads();
            #pragma unroll
            for (int rr = 0; rr < 4; rr++) {
                int r = rr * 8 + ty;
                W1T[(tc * 32 + r) * CCH + tr * 32 + tx] = tile[tx][r];
            }
            __syncthreads();
        }
        // W2: 4x8 = 32 tiles of 32x32  (rows = o in [0,128), cols = k)
        for (int t = hb; t < 32; t += NHELP) {
            const int tr = t >> 3, tc = t & 7;
            #pragma unroll
            for (int rr = 0; rr < 4; rr++) {
                int r = rr * 8 + ty;
                tile[r][tx] = W2[(tr * 32 + r) * CCH + tc * 32 + tx];
            }
            __syncthreads();
            #pragma unroll
            for (int rr = 0; rr < 4; rr++) {
                int r = rr * 8 + ty;
                W2T[(tc * 32 + r) * ENC + tr * 32 + tx] = tile[tx][r];
            }
            __syncthreads();
        }
        return;
    }

    const float* __restrict__ feat = br ? f2 : f1;
    const float* __restrict__ cw   = br ? w_dep : w_img;
    const float  bias              = br ? b_dep[0] : b_img[0];

    ws[tid] = cw[tid];
    __syncthreads();

    const int g     = blockIdx.x * 256 + tid;   // position-pair index
    const int pos   = g * 2;
    const int plane = pos % PLANE;
    const int b     = pos / PLANE;

    const float* __restrict__ base =
        feat + (size_t)b * CCH * PLANE + plane;

    float a0 = 0.f, a1 = 0.f;
    #pragma unroll 8
    for (int c = 0; c < CCH; c++) {
        float2 v = __ldcs(reinterpret_cast<const float2*>(base + (size_t)c * PLANE));
        float  w = ws[c];
        a0 = fmaf(w, v.x, a0);
        a1 = fmaf(w, v.y, a1);
    }
    a0 = fmaxf(a0 + bias, 0.f);
    a1 = fmaxf(a1 + bias, 0.f);

    const int y  = plane / HW;
    const int x  = plane % HW;                 // even
    const int pv = y >> 4, i = y & 15;
    const int ph = x >> 4, j = x & 15;         // j even, j+1 same patch
    const int p  = (b * NGRID + pv) * NGRID + ph;
    float2 o; o.x = a0; o.y = a1;
    *reinterpret_cast<float2*>(&g_X[br][(p << 8) + (i << 4) + j]) = o;
}

// ---------------------------------------------------------------------------
// Kernel B (R9-validated body): per-branch MLP relu(X @ W1^T) @ W2^T +
// LayerNorm(128). grid = (50, 2), block = 256, 8 rows per block.
// Weights read from pre-transposed g_W1T/g_W2T with lane-consecutive
// addresses -> 1 L1tex wavefront per warp-load instead of 32.
// ---------------------------------------------------------------------------
__global__ void __launch_bounds__(256)
mlp_kernel(const float* __restrict__ g_img,
           const float* __restrict__ be_img,
           const float* __restrict__ g_dep,
           const float* __restrict__ be_dep)
{
    const int br = blockIdx.y;
    const float* __restrict__ W1T = g_W1T[br];
    const float* __restrict__ W2T = g_W2T[br];
    const float* __restrict__ lng = br ? g_dep  : g_img;
    const float* __restrict__ lnb = br ? be_dep : be_img;

    const int row0 = blockIdx.x * BR;
    const int tid  = threadIdx.x;

    __shared__ float xsT[CCH * BR];   // [k][r]
    __shared__ float hsT[CCH * BR];   // [k][r]
    __shared__ float os [BR * ENC];   // [r][o]

    // load X rows transposed
    for (int t = tid; t < CCH * BR; t += 256) {
        int r = t >> 8, k = t & 255;
        xsT[k * BR + r] = g_X[br][(row0 + r) * CCH + k];
    }
    __syncthreads();

    // GEMM1: h[r][j] = relu( sum_k x[r][k] * W1T[k][j] ),  j = tid
    {
        const int j = tid;
        const float* __restrict__ wp = W1T + j;   // lane-consecutive per k
        float acc[BR];
        #pragma unroll
        for (int r = 0; r < BR; r++) acc[r] = 0.f;

        #pragma unroll 8
        for (int k = 0; k < CCH; k++) {
            float  w  = __ldg(wp + k * CCH);      // coalesced: 1 wf per warp
            float4 xa = *reinterpret_cast<const float4*>(&xsT[k * BR]);
            float4 xb = *reinterpret_cast<const float4*>(&xsT[k * BR + 4]);
            acc[0] = fmaf(w, xa.x, acc[0]);
            acc[1] = fmaf(w, xa.y, acc[1]);
            acc[2] = fmaf(w, xa.z, acc[2]);
            acc[3] = fmaf(w, xa.w, acc[3]);
            acc[4] = fmaf(w, xb.x, acc[4]);
            acc[5] = fmaf(w, xb.y, acc[5]);
            acc[6] = fmaf(w, xb.z, acc[6]);
            acc[7] = fmaf(w, xb.w, acc[7]);
        }
        float4 h0, h1;
        h0.x = fmaxf(acc[0], 0.f); h0.y = fmaxf(acc[1], 0.f);
        h0.z = fmaxf(acc[2], 0.f); h0.w = fmaxf(acc[3], 0.f);
        h1.x = fmaxf(acc[4], 0.f); h1.y = fmaxf(acc[5], 0.f);
        h1.z = fmaxf(acc[6], 0.f); h1.w = fmaxf(acc[7], 0.f);
        *reinterpret_cast<float4*>(&hsT[j * BR])     = h0;
        *reinterpret_cast<float4*>(&hsT[j * BR + 4]) = h1;
    }
    __syncthreads();

    // GEMM2: out[r][o] = sum_k h[r][k] * W2T[k][o]
    {
        const int o  = tid & 127;
        const int rb = (tid >> 7) * 4;            // 0 or 4
        const float* __restrict__ wp = W2T + o;   // lane-consecutive per k
        float acc[4] = {0.f, 0.f, 0.f, 0.f};

        #pragma unroll 8
        for (int k = 0; k < CCH; k++) {
            float  w  = __ldg(wp + k * ENC);
            float4 hv = *reinterpret_cast<const float4*>(&hsT[k * BR + rb]);
            acc[0] = fmaf(w, hv.x, acc[0]);
            acc[1] = fmaf(w, hv.y, acc[1]);
            acc[2] = fmaf(w, hv.z, acc[2]);
            acc[3] = fmaf(w, hv.w, acc[3]);
        }
        #pragma unroll
        for (int i = 0; i < 4; i++)
            os[(rb + i) * ENC + o] = acc[i];
    }
    __syncthreads();

    // LayerNorm: warp w handles row w
    {
        const int w    = tid >> 5;
        const int lane = tid & 31;
        float4 v = *reinterpret_cast<const float4*>(&os[w * ENC + lane * 4]);
        float s = v.x + v.y + v.z + v.w;
        float q = v.x * v.x + v.y * v.y + v.z * v.z + v.w * v.w;
        #pragma unroll
        for (int off = 16; off; off >>= 1) {
            s += __shfl_xor_sync(0xffffffffu, s, off);
            q += __shfl_xor_sync(0xffffffffu, q, off);
        }
        const float mu  = s * (1.f / 128.f);
        const float var = q * (1.f / 128.f) - mu * mu;
        const float rs  = rsqrtf(var + 1e-5f);
        float4 g4 = *reinterpret_cast<const float4*>(lng + lane * 4);
        float4 b4 = *reinterpret_cast<const float4*>(lnb + lane * 4);
        float4 e;
        e.x = (v.x - mu) * rs * g4.x + b4.x;
        e.y = (v.y - mu) * rs * g4.y + b4.y;
        e.z = (v.z - mu) * rs * g4.z + b4.z;
        e.w = (v.w - mu) * rs * g4.w + b4.w;
        *reinterpret_cast<float4*>(&g_E[br][(row0 + w) * ENC + lane * 4]) = e;
    }
}

// ---------------------------------------------------------------------------
// Kernel C (R3-proven, verbatim): logits[b,n,m] = exp(ls)*dot(e1[b,n],e2[b,m]);
// writes both orderings. grid = (100 n, 4 b), block = 128 (4 warps x 25 m).
// ---------------------------------------------------------------------------
__global__ void logits_kernel(const float* __restrict__ lsc,
                              float* __restrict__ out)
{
    const int n    = blockIdx.x;
    const int b    = blockIdx.y;
    const int tid  = threadIdx.x;
    const int wp   = tid >> 5;
    const int lane = tid & 31;

    __shared__ float e1s[ENC];
    e1s[tid] = g_E[0][(b * NPATCH + n) * ENC + tid];
    __syncthreads();

    const float scale = expf(lsc[0]);
    const float4 a = reinterpret_cast<const float4*>(e1s)[lane];

    const int m0 = wp * 25;
    for (int m = m0; m < m0 + 25; m++) {
        float4 v = *reinterpret_cast<const float4*>(
            &g_E[1][(b * NPATCH + m) * ENC + lane * 4]);
        float s = a.x * v.x + a.y * v.y + a.z * v.z + a.w * v.w;
        #pragma unroll
        for (int off = 16; off; off >>= 1)
            s += __shfl_xor_sync(0xffffffffu, s, off);
        if (lane == 0) {
            float val = scale * s;
            out[(b * NPATCH + n) * NPATCH + m] = val;                       // bnm
            out[BATCH * NPATCH * NPATCH + (b * NPATCH + m) * NPATCH + n] = val;  // bmn
        }
    }
}

// ---------------------------------------------------------------------------
extern "C" void kernel_launch(void* const* d_in, const int* in_sizes, int n_in,
                              void* d_out, int out_size)
{
    const float* f1  = (const float*)d_in[0];   // feat_c1
    const float* f2  = (const float*)d_in[1];   // feat_c2
    // d_in[2] = mask_c1 (all ones; grid static: nv=nh=10)
    const float* icw = (const float*)d_in[3];   // img_conv_w
    const float* icb = (const float*)d_in[4];   // img_conv_b
    const float* iw1 = (const float*)d_in[5];   // img_w1
    const float* iw2 = (const float*)d_in[6];   // img_w2
    const float* ig  = (const float*)d_in[7];   // img_ln_g
    const float* ib  = (const float*)d_in[8];   // img_ln_b
    const float* dcw = (const float*)d_in[9];   // depth_conv_w
    const float* dcb = (const float*)d_in[10];  // depth_conv_b
    const float* dw1 = (const float*)d_in[11];  // depth_w1
    const float* dw2 = (const float*)d_in[12];  // depth_w2
    const float* dg  = (const float*)d_in[13];  // depth_ln_g
    const float* db  = (const float*)d_in[14];  // depth_ln_b
    const float* ls  = (const float*)d_in[15];  // logit_scale

    conv_kernel  <<<dim3(200 + NHELP, 2), 256>>>(f1, f2, icw, icb, dcw, dcb,
                                                 iw1, iw2, dw1, dw2);
    mlp_kernel   <<<dim3(50, 2), 256>>>(ig, ib, dg, db);
    logits_kernel<<<dim3(100, 4), 128>>>(ls, (float*)d_out);
}

// round 15
// speedup vs baseline: 1.0143x; 1.0143x over previous
#include <cuda_runtime.h>
#include <cstdint>

#define CPS    16
#define ENC    128
#define BATCH  4
#define HW     160
#define PLANE  (HW * HW)          // 25600
#define NGRID  10
#define NPATCH 100
#define NROWS  (BATCH * NPATCH)   // 400
#define CCH    256
#define BR     8                  // rows per MLP block
#define NBLK   400                // total blocks (all co-resident: >=2.7/SM)

// Scratch (allocation-free)
__device__ float g_X[2][NROWS * CCH];
__device__ float g_E[2][NROWS * ENC];
__device__ int   g_ctrA, g_ctrB, g_ctrC;   // zeroed at end of each launch

// ---------------------------------------------------------------------------
// Grid barrier with GENTLE polling: one poller per block, 2us sleep between
// polls => aggregate ~0.2G same-line reads/s (vs R8's 6G/s storm that
// serialized the LTS and contaminated phases B/C). Overshoot <=2us, hidden
// under the conv-phase block-finish spread.
// ---------------------------------------------------------------------------
__device__ __forceinline__ void grid_barrier(int* ctr)
{
    __syncthreads();
    if (threadIdx.x == 0) {
        __threadfence();                  // release this phase's writes
        atomicAdd(ctr, 1);
        while (*(volatile int*)ctr < NBLK) __nanosleep(2048);
    }
    __syncthreads();
}

// ---------------------------------------------------------------------------
// ONE fused kernel: conv -> barrier -> mlp -> barrier -> logits.
// 400 blocks x 256 threads. Phase bodies are the round-proven versions.
// ---------------------------------------------------------------------------
__global__ void __launch_bounds__(256)
fused_kernel(const float* __restrict__ f1,
             const float* __restrict__ f2,
             const float* __restrict__ w_img,
             const float* __restrict__ b_img,
             const float* __restrict__ w_dep,
             const float* __restrict__ b_dep,
             const float* __restrict__ w1_img,
             const float* __restrict__ w2_img,
             const float* __restrict__ g_img,
             const float* __restrict__ be_img,
             const float* __restrict__ w1_dep,
             const float* __restrict__ w2_dep,
             const float* __restrict__ g_dep,
             const float* __restrict__ be_dep,
             const float* __restrict__ lsc,
             float* __restrict__ out)
{
    __shared__ float smem[CCH * BR * 2 + BR * ENC];   // 5120 floats = 20 KB
    const int tid = threadIdx.x;
    const int bid = blockIdx.x;

    // ======================= Phase A: conv (R7-proven) ======================
    {
        const int cx = bid % 200;
        const int br = bid / 200;
        const float* __restrict__ feat = br ? f2 : f1;
        const float* __restrict__ cw   = br ? w_dep : w_img;
        const float  bias              = br ? b_dep[0] : b_img[0];

        float* ws = smem;                 // 256 floats
        ws[tid] = cw[tid];
        __syncthreads();

        const int g     = cx * 256 + tid;     // position-pair index
        const int pos   = g * 2;
        const int plane = pos % PLANE;
        const int b     = pos / PLANE;

        const float* __restrict__ base =
            feat + (size_t)b * CCH * PLANE + plane;

        float a0 = 0.f, a1 = 0.f;
        #pragma unroll 8
        for (int c = 0; c < CCH; c++) {
            float2 v = __ldcs(reinterpret_cast<const float2*>(base + (size_t)c * PLANE));
            float  w = ws[c];
            a0 = fmaf(w, v.x, a0);
            a1 = fmaf(w, v.y, a1);
        }
        a0 = fmaxf(a0 + bias, 0.f);
        a1 = fmaxf(a1 + bias, 0.f);

        const int y  = plane / HW;
        const int x  = plane % HW;           // even
        const int pv = y >> 4, i = y & 15;
        const int ph = x >> 4, j = x & 15;
        const int p  = (b * NGRID + pv) * NGRID + ph;
        float2 o; o.x = a0; o.y = a1;
        *reinterpret_cast<float2*>(&g_X[br][(p << 8) + (i << 4) + j]) = o;
    }

    grid_barrier(&g_ctrA);

    // ======================= Phase B: mlp (R3-proven), blocks 0-99 ==========
    if (bid < 100) {
        const int br = bid / 50;
        const float* __restrict__ W1  = br ? w1_dep : w1_img;
        const float* __restrict__ W2  = br ? w2_dep : w2_img;
        const float* __restrict__ lng = br ? g_dep  : g_img;
        const float* __restrict__ lnb = br ? be_dep : be_img;

        const int row0 = (bid % 50) * BR;

        float* xsT = smem;                   // [k][r]  2048
        float* hsT = smem + CCH * BR;        // [k][r]  2048
        float* os  = smem + CCH * BR * 2;    // [r][o]  1024

        for (int t = tid; t < CCH * BR; t += 256) {
            int r = t >> 8, k = t & 255;
            xsT[k * BR + r] = g_X[br][(row0 + r) * CCH + k];
        }
        __syncthreads();

        // GEMM1: h[r][j] = relu( sum_k x[r][k] * W1[j][k] ), j = tid
        {
            const int j = tid;
            const float4* __restrict__ w1r =
                reinterpret_cast<const float4*>(W1 + j * CCH);
            float acc[BR];
            #pragma unroll
            for (int r = 0; r < BR; r++) acc[r] = 0.f;

            #pragma unroll 4
            for (int k4 = 0; k4 < CCH / 4; k4++) {
                float4 w = w1r[k4];
                float wv[4]; wv[0] = w.x; wv[1] = w.y; wv[2] = w.z; wv[3] = w.w;
                const float* xk = &xsT[k4 * 4 * BR];
                #pragma unroll
                for (int kk = 0; kk < 4; kk++) {
                    float  c  = wv[kk];
                    float4 xa = *reinterpret_cast<const float4*>(xk + kk * BR);
                    float4 xb = *reinterpret_cast<const float4*>(xk + kk * BR + 4);
                    acc[0] = fmaf(c, xa.x, acc[0]);
                    acc[1] = fmaf(c, xa.y, acc[1]);
                    acc[2] = fmaf(c, xa.z, acc[2]);
                    acc[3] = fmaf(c, xa.w, acc[3]);
                    acc[4] = fmaf(c, xb.x, acc[4]);
                    acc[5] = fmaf(c, xb.y, acc[5]);
                    acc[6] = fmaf(c, xb.z, acc[6]);
                    acc[7] = fmaf(c, xb.w, acc[7]);
                }
            }
            float4 h0, h1;
            h0.x = fmaxf(acc[0], 0.f); h0.y = fmaxf(acc[1], 0.f);
            h0.z = fmaxf(acc[2], 0.f); h0.w = fmaxf(acc[3], 0.f);
            h1.x = fmaxf(acc[4], 0.f); h1.y = fmaxf(acc[5], 0.f);
            h1.z = fmaxf(acc[6], 0.f); h1.w = fmaxf(acc[7], 0.f);
            *reinterpret_cast<float4*>(&hsT[j * BR])     = h0;
            *reinterpret_cast<float4*>(&hsT[j * BR + 4]) = h1;
        }
        __syncthreads();

        // GEMM2: out[r][o] = sum_k h[r][k] * W2[o][k]
        {
            const int o  = tid & 127;
            const int rb = (tid >> 7) * 4;
            const float4* __restrict__ w2r =
                reinterpret_cast<const float4*>(W2 + o * CCH);
            float acc[4] = {0.f, 0.f, 0.f, 0.f};

            #pragma unroll 4
            for (int k4 = 0; k4 < CCH / 4; k4++) {
                float4 w = w2r[k4];
                float wv[4]; wv[0] = w.x; wv[1] = w.y; wv[2] = w.z; wv[3] = w.w;
                const float* hk = &hsT[k4 * 4 * BR + rb];
                #pragma unroll
                for (int kk = 0; kk < 4; kk++) {
                    float  c  = wv[kk];
                    float4 hv = *reinterpret_cast<const float4*>(hk + kk * BR);
                    acc[0] = fmaf(c, hv.x, acc[0]);
                    acc[1] = fmaf(c, hv.y, acc[1]);
                    acc[2] = fmaf(c, hv.z, acc[2]);
                    acc[3] = fmaf(c, hv.w, acc[3]);
                }
            }
            #pragma unroll
            for (int i = 0; i < 4; i++)
                os[(rb + i) * ENC + o] = acc[i];
        }
        __syncthreads();

        // LayerNorm: warp w handles row w
        {
            const int w    = tid >> 5;
            const int lane = tid & 31;
            float4 v = *reinterpret_cast<const float4*>(&os[w * ENC + lane * 4]);
            float s = v.x + v.y + v.z + v.w;
            float q = v.x * v.x + v.y * v.y + v.z * v.z + v.w * v.w;
            #pragma unroll
            for (int off = 16; off; off >>= 1) {
                s += __shfl_xor_sync(0xffffffffu, s, off);
                q += __shfl_xor_sync(0xffffffffu, q, off);
            }
            const float mu  = s * (1.f / 128.f);
            const float var = q * (1.f / 128.f) - mu * mu;
            const float rs  = rsqrtf(var + 1e-5f);
            float4 g4 = *reinterpret_cast<const float4*>(lng + lane * 4);
            float4 b4 = *reinterpret_cast<const float4*>(lnb + lane * 4);
            float4 e;
            e.x = (v.x - mu) * rs * g4.x + b4.x;
            e.y = (v.y - mu) * rs * g4.y + b4.y;
            e.z = (v.z - mu) * rs * g4.z + b4.z;
            e.w = (v.w - mu) * rs * g4.w + b4.w;
            *reinterpret_cast<float4*>(&g_E[br][(row0 + w) * ENC + lane * 4]) = e;
        }
    }

    grid_barrier(&g_ctrB);

    // ======================= Phase C: logits, 1 (b,n) per block =============
    {
        const int b    = bid / NPATCH;
        const int n    = bid % NPATCH;
        const int wp   = tid >> 5;
        const int lane = tid & 31;

        float* e1s = smem;                   // 128 floats
        if (tid < ENC)
            e1s[tid] = g_E[0][(b * NPATCH + n) * ENC + tid];
        __syncthreads();

        const float scale = expf(lsc[0]);
        const float4 a = reinterpret_cast<const float4*>(e1s)[lane];

        // 8 warps x 13 m (covers 100)
        const int m0   = wp * 13;
        const int mend = (m0 + 13 < NPATCH) ? m0 + 13 : NPATCH;
        for (int m = m0; m < mend; m++) {
            float4 v = *reinterpret_cast<const float4*>(
                &g_E[1][(b * NPATCH + m) * ENC + lane * 4]);
            float s = a.x * v.x + a.y * v.y + a.z * v.z + a.w * v.w;
            #pragma unroll
            for (int off = 16; off; off >>= 1)
                s += __shfl_xor_sync(0xffffffffu, s, off);
            if (lane == 0) {
                float val = scale * s;
                out[(b * NPATCH + n) * NPATCH + m] = val;                        // bnm
                out[BATCH * NPATCH * NPATCH + (b * NPATCH + m) * NPATCH + n] = val;  // bmn
            }
        }
    }

    // ======================= Finish: count + reset (replay-safe) ============
    __syncthreads();
    if (tid == 0) {
        __threadfence();
        atomicAdd(&g_ctrC, 1);
        if (bid == 0) {
            while (*(volatile int*)&g_ctrC < NBLK) __nanosleep(2048);
            g_ctrA = 0; g_ctrB = 0; g_ctrC = 0;
            __threadfence();
        }
    }
}

// ---------------------------------------------------------------------------
extern "C" void kernel_launch(void* const* d_in, const int* in_sizes, int n_in,
                              void* d_out, int out_size)
{
    const float* f1  = (const float*)d_in[0];   // feat_c1
    const float* f2  = (const float*)d_in[1];   // feat_c2
    // d_in[2] = mask_c1 (all ones; grid static: nv=nh=10)
    const float* icw = (const float*)d_in[3];   // img_conv_w
    const float* icb = (const float*)d_in[4];   // img_conv_b
    const float* iw1 = (const float*)d_in[5];   // img_w1
    const float* iw2 = (const float*)d_in[6];   // img_w2
    const float* ig  = (const float*)d_in[7];   // img_ln_g
    const float* ib  = (const float*)d_in[8];   // img_ln_b
    const float* dcw = (const float*)d_in[9];   // depth_conv_w
    const float* dcb = (const float*)d_in[10];  // depth_conv_b
    const float* dw1 = (const float*)d_in[11];  // depth_w1
    const float* dw2 = (const float*)d_in[12];  // depth_w2
    const float* dg  = (const float*)d_in[13];  // depth_ln_g
    const float* db  = (const float*)d_in[14];  // depth_ln_b
    const float* ls  = (const float*)d_in[15];  // logit_scale

    fused_kernel<<<NBLK, 256>>>(f1, f2, icw, icb, dcw, dcb,
                                iw1, iw2, ig, ib,
                                dw1, dw2, dg, db,
                                ls, (float*)d_out);
}

// round 17
// speedup vs baseline: 1.2262x; 1.2090x over previous
#include <cuda_runtime.h>
#include <cstdint>

#define CPS    16
#define ENC    128
#define BATCH  4
#define HW     160
#define PLANE  (HW * HW)          // 25600
#define NGRID  10
#define NPATCH 100
#define NROWS  (BATCH * NPATCH)   // 400
#define CCH    256
#define BR     8                  // rows per MLP block
#define CBATCH 16                 // conv load-batch depth (explicit MLP)

// Scratch (allocation-free): conv output X (2 branches x 400 x 256),
// embeddings E (2 branches x 400 x 128)
__device__ float g_X[2][NROWS * CCH];
__device__ float g_E[2][NROWS * ENC];

// ---------------------------------------------------------------------------
// Kernel A: 1x1 conv + bias + relu, patch-reordered write. R7 layout
// (256 thr x float2 = 2KB grain/step, grid (200,2), __ldcs) with one change:
// EXPLICIT load batching — 16 float2 loaded into a register array before any
// FMA consumes them, forcing ~4KB in flight per warp (~86KB/SM at 21.6
// warps/SM) instead of the ~1KB ptxas schedules from a fused loop.
// __launch_bounds__(256,4) => 64 regs available so the batch fits.
// ---------------------------------------------------------------------------
__global__ void __launch_bounds__(256, 4)
conv_kernel(const float* __restrict__ f1,
            const float* __restrict__ f2,
            const float* __restrict__ w_img,
            const float* __restrict__ b_img,
            const float* __restrict__ w_dep,
            const float* __restrict__ b_dep)
{
    const int br  = blockIdx.y;
    const float* __restrict__ feat = br ? f2 : f1;
    const float* __restrict__ cw   = br ? w_dep : w_img;
    const float  bias              = br ? b_dep[0] : b_img[0];

    __shared__ float ws[CCH];
    const int tid = threadIdx.x;
    ws[tid] = cw[tid];
    __syncthreads();

    const int g     = blockIdx.x * 256 + tid;   // position-pair index
    const int pos   = g * 2;
    const int plane = pos % PLANE;
    const int b     = pos / PLANE;

    const float* __restrict__ base =
        feat + (size_t)b * CCH * PLANE + plane;

    float a0 = 0.f, a1 = 0.f;
    for (int c0 = 0; c0 < CCH; c0 += CBATCH) {
        float2 v[CBATCH];
        #pragma unroll
        for (int u = 0; u < CBATCH; u++)
            v[u] = __ldcs(reinterpret_cast<const float2*>(
                        base + (size_t)(c0 + u) * PLANE));
        #pragma unroll
        for (int u = 0; u < CBATCH; u++) {
            float w = ws[c0 + u];
            a0 = fmaf(w, v[u].x, a0);
            a1 = fmaf(w, v[u].y, a1);
        }
    }
    a0 = fmaxf(a0 + bias, 0.f);
    a1 = fmaxf(a1 + bias, 0.f);

    const int y  = plane / HW;
    const int x  = plane % HW;                 // even
    const int pv = y >> 4, i = y & 15;
    const int ph = x >> 4, j = x & 15;         // j even, j+1 same patch
    const int p  = (b * NGRID + pv) * NGRID + ph;
    float2 o; o.x = a0; o.y = a1;
    *reinterpret_cast<float2*>(&g_X[br][(p << 8) + (i << 4) + j]) = o;
}

// ---------------------------------------------------------------------------
// Kernel B (R3-proven, verbatim): per-branch MLP relu(X @ W1^T) @ W2^T +
// LayerNorm(128). grid = (50, 2), block = 256, 8 rows per block.
// ---------------------------------------------------------------------------
__global__ void mlp_kernel(const float* __restrict__ w1_img,
                           const float* __restrict__ w2_img,
                           const float* __restrict__ g_img,
                           const float* __restrict__ be_img,
                           const float* __restrict__ w1_dep,
                           const float* __restrict__ w2_dep,
                           const float* __restrict__ g_dep,
                           const float* __restrict__ be_dep)
{
    const int br = blockIdx.y;
    const float* __restrict__ W1  = br ? w1_dep : w1_img;
    const float* __restrict__ W2  = br ? w2_dep : w2_img;
    const float* __restrict__ lng = br ? g_dep  : g_img;
    const float* __restrict__ lnb = br ? be_dep : be_img;

    const int row0 = blockIdx.x * BR;
    const int tid  = threadIdx.x;

    __shared__ float xsT[CCH * BR];   // [k][r]
    __shared__ float hsT[CCH * BR];   // [k][r]
    __shared__ float os [BR * ENC];   // [r][o]

    // load X rows transposed
    for (int t = tid; t < CCH * BR; t += 256) {
        int r = t >> 8, k = t & 255;
        xsT[k * BR + r] = g_X[br][(row0 + r) * CCH + k];
    }
    __syncthreads();

    // GEMM1: h[r][j] = relu( sum_k x[r][k] * W1[j][k] ),  j = tid
    {
        const int j = tid;
        const float4* __restrict__ w1r =
            reinterpret_cast<const float4*>(W1 + j * CCH);
        float acc[BR];
        #pragma unroll
        for (int r = 0; r < BR; r++) acc[r] = 0.f;

        #pragma unroll 4
        for (int k4 = 0; k4 < CCH / 4; k4++) {
            float4 w = w1r[k4];
            float wv[4]; wv[0] = w.x; wv[1] = w.y; wv[2] = w.z; wv[3] = w.w;
            const float* xk = &xsT[k4 * 4 * BR];
            #pragma unroll
            for (int kk = 0; kk < 4; kk++) {
                float  c  = wv[kk];
                float4 xa = *reinterpret_cast<const float4*>(xk + kk * BR);
                float4 xb = *reinterpret_cast<const float4*>(xk + kk * BR + 4);
                acc[0] = fmaf(c, xa.x, acc[0]);
                acc[1] = fmaf(c, xa.y, acc[1]);
                acc[2] = fmaf(c, xa.z, acc[2]);
                acc[3] = fmaf(c, xa.w, acc[3]);
                acc[4] = fmaf(c, xb.x, acc[4]);
                acc[5] = fmaf(c, xb.y, acc[5]);
                acc[6] = fmaf(c, xb.z, acc[6]);
                acc[7] = fmaf(c, xb.w, acc[7]);
            }
        }
        float4 h0, h1;
        h0.x = fmaxf(acc[0], 0.f); h0.y = fmaxf(acc[1], 0.f);
        h0.z = fmaxf(acc[2], 0.f); h0.w = fmaxf(acc[3], 0.f);
        h1.x = fmaxf(acc[4], 0.f); h1.y = fmaxf(acc[5], 0.f);
        h1.z = fmaxf(acc[6], 0.f); h1.w = fmaxf(acc[7], 0.f);
        *reinterpret_cast<float4*>(&hsT[j * BR])     = h0;
        *reinterpret_cast<float4*>(&hsT[j * BR + 4]) = h1;
    }
    __syncthreads();

    // GEMM2: out[r][o] = sum_k h[r][k] * W2[o][k]
    {
        const int o    = tid & 127;
        const int rb   = (tid >> 7) * 4;        // 0 or 4
        const float4* __restrict__ w2r =
            reinterpret_cast<const float4*>(W2 + o * CCH);
        float acc[4] = {0.f, 0.f, 0.f, 0.f};

        #pragma unroll 4
        for (int k4 = 0; k4 < CCH / 4; k4++) {
            float4 w = w2r[k4];
            float wv[4]; wv[0] = w.x; wv[1] = w.y; wv[2] = w.z; wv[3] = w.w;
            const float* hk = &hsT[k4 * 4 * BR + rb];
            #pragma unroll
            for (int kk = 0; kk < 4; kk++) {
                float  c  = wv[kk];
                float4 hv = *reinterpret_cast<const float4*>(hk + kk * BR);
                acc[0] = fmaf(c, hv.x, acc[0]);
                acc[1] = fmaf(c, hv.y, acc[1]);
                acc[2] = fmaf(c, hv.z, acc[2]);
                acc[3] = fmaf(c, hv.w, acc[3]);
            }
        }
        #pragma unroll
        for (int i = 0; i < 4; i++)
            os[(rb + i) * ENC + o] = acc[i];
    }
    __syncthreads();

    // LayerNorm: warp w handles row w
    {
        const int w    = tid >> 5;
        const int lane = tid & 31;
        float4 v = *reinterpret_cast<const float4*>(&os[w * ENC + lane * 4]);
        float s = v.x + v.y + v.z + v.w;
        float q = v.x * v.x + v.y * v.y + v.z * v.z + v.w * v.w;
        #pragma unroll
        for (int off = 16; off; off >>= 1) {
            s += __shfl_xor_sync(0xffffffffu, s, off);
            q += __shfl_xor_sync(0xffffffffu, q, off);
        }
        const float mu  = s * (1.f / 128.f);
        const float var = q * (1.f / 128.f) - mu * mu;
        const float rs  = rsqrtf(var + 1e-5f);
        float4 g4 = *reinterpret_cast<const float4*>(lng + lane * 4);
        float4 b4 = *reinterpret_cast<const float4*>(lnb + lane * 4);
        float4 e;
        e.x = (v.x - mu) * rs * g4.x + b4.x;
        e.y = (v.y - mu) * rs * g4.y + b4.y;
        e.z = (v.z - mu) * rs * g4.z + b4.z;
        e.w = (v.w - mu) * rs * g4.w + b4.w;
        *reinterpret_cast<float4*>(&g_E[br][(row0 + w) * ENC + lane * 4]) = e;
    }
}

// ---------------------------------------------------------------------------
// Kernel C (R3-proven, verbatim): logits[b,n,m] = exp(ls)*dot(e1[b,n],e2[b,m]);
// writes both orderings. grid = (100 n, 4 b), block = 128 (4 warps x 25 m).
// ---------------------------------------------------------------------------
__global__ void logits_kernel(const float* __restrict__ lsc,
                              float* __restrict__ out)
{
    const int n    = blockIdx.x;
    const int b    = blockIdx.y;
    const int tid  = threadIdx.x;
    const int wp   = tid >> 5;
    const int lane = tid & 31;

    __shared__ float e1s[ENC];
    e1s[tid] = g_E[0][(b * NPATCH + n) * ENC + tid];
    __syncthreads();

    const float scale = expf(lsc[0]);
    const float4 a = reinterpret_cast<const float4*>(e1s)[lane];

    const int m0 = wp * 25;
    for (int m = m0; m < m0 + 25; m++) {
        float4 v = *reinterpret_cast<const float4*>(
            &g_E[1][(b * NPATCH + m) * ENC + lane * 4]);
        float s = a.x * v.x + a.y * v.y + a.z * v.z + a.w * v.w;
        #pragma unroll
        for (int off = 16; off; off >>= 1)
            s += __shfl_xor_sync(0xffffffffu, s, off);
        if (lane == 0) {
            float val = scale * s;
            out[(b * NPATCH + n) * NPATCH + m] = val;                       // bnm
            out[BATCH * NPATCH * NPATCH + (b * NPATCH + m) * NPATCH + n] = val;  // bmn
        }
    }
}

// ---------------------------------------------------------------------------
extern "C" void kernel_launch(void* const* d_in, const int* in_sizes, int n_in,
                              void* d_out, int out_size)
{
    const float* f1  = (const float*)d_in[0];   // feat_c1
    const float* f2  = (const float*)d_in[1];   // feat_c2
    // d_in[2] = mask_c1 (all ones; grid static: nv=nh=10)
    const float* icw = (const float*)d_in[3];   // img_conv_w
    const float* icb = (const float*)d_in[4];   // img_conv_b
    const float* iw1 = (const float*)d_in[5];   // img_w1
    const float* iw2 = (const float*)d_in[6];   // img_w2
    const float* ig  = (const float*)d_in[7];   // img_ln_g
    const float* ib  = (const float*)d_in[8];   // img_ln_b
    const float* dcw = (const float*)d_in[9];   // depth_conv_w
    const float* dcb = (const float*)d_in[10];  // depth_conv_b
    const float* dw1 = (const float*)d_in[11];  // depth_w1
    const float* dw2 = (const float*)d_in[12];  // depth_w2
    const float* dg  = (const float*)d_in[13];  // depth_ln_g
    const float* db  = (const float*)d_in[14];  // depth_ln_b
    const float* ls  = (const float*)d_in[15];  // logit_scale

    conv_kernel  <<<dim3(200, 2), 256>>>(f1, f2, icw, icb, dcw, dcb);
    mlp_kernel   <<<dim3(50, 2), 256>>>(iw1, iw2, ig, ib, dw1, dw2, dg, db);
    logits_kernel<<<dim3(100, 4), 128>>>(ls, (float*)d_out);
}